// round 1
// baseline (speedup 1.0000x reference)
#include <cuda_runtime.h>
#include <math.h>

// Problem max sizes (registry shapes: N=50000, E=800000)
#define NMAX 50000
#define EMAX 800000
#define EPMAX (NMAX + EMAX)

// Scratch (static device globals — no allocation allowed)
__device__ float    g_z[NMAX * 64];       // node features @ W (pre-aggregation)
__device__ float    g_h[NMAX * 64];       // node hidden state (layer output)
__device__ float    g_out[NMAX * 64];     // aggregation accumulator
__device__ float    g_alpha[EPMAX * 2];   // per-edge, per-head attention logits
__device__ unsigned g_m[NMAX * 2];        // segment max (ordered-uint encoded)
__device__ float    g_denom[NMAX * 2];    // segment sum of exp
__device__ double   g_easum[2];           // edge_attr column sums (double)
__device__ float    g_eamean[2];          // edge_attr column means
__device__ float    g_u[NMAX * 32];       // h @ Wm1[0:64]
__device__ float    g_v[NMAX * 32];       // h @ Wm1[64:128]
__device__ float    g_gvec[32];           // goal @ Wm1[128:192] + bm1

// ---- float <-> orderable uint (for atomicMax on floats) ----
__device__ __forceinline__ unsigned f2o(float f) {
    unsigned u = __float_as_uint(f);
    return (u & 0x80000000u) ? ~u : (u | 0x80000000u);
}
__device__ __forceinline__ float o2f(unsigned u) {
    return __uint_as_float((u & 0x80000000u) ? (u & 0x7fffffffu) : ~u);
}

// ============================================================
// edge_attr mean (double accumulation for accuracy)
// ============================================================
__global__ void k_easum_init() {
    if (threadIdx.x < 2) g_easum[threadIdx.x] = 0.0;
}

__global__ void k_easum(const float2* __restrict__ ea, int E) {
    double s0 = 0.0, s1 = 0.0;
    for (int i = blockIdx.x * blockDim.x + threadIdx.x; i < E;
         i += gridDim.x * blockDim.x) {
        float2 v = ea[i];
        s0 += (double)v.x;
        s1 += (double)v.y;
    }
    __shared__ double sh0[256], sh1[256];
    int t = threadIdx.x;
    sh0[t] = s0; sh1[t] = s1;
    __syncthreads();
    for (int ofs = 128; ofs > 0; ofs >>= 1) {
        if (t < ofs) { sh0[t] += sh0[t + ofs]; sh1[t] += sh1[t + ofs]; }
        __syncthreads();
    }
    if (t == 0) {
        atomicAdd(&g_easum[0], sh0[0]);
        atomicAdd(&g_easum[1], sh1[0]);
    }
}

__global__ void k_eamean(int E) {
    if (threadIdx.x < 2)
        g_eamean[threadIdx.x] = (float)(g_easum[threadIdx.x] / (double)E);
}

// ============================================================
// z = h @ W + b
// ============================================================
__global__ void k_z0(const float* __restrict__ x, const float* __restrict__ W,
                     const float* __restrict__ b, int N) {
    int i = blockIdx.x * blockDim.x + threadIdx.x;
    if (i >= N * 64) return;
    int n = i >> 6, j = i & 63;
    g_z[i] = fmaf(x[2 * n], W[j], fmaf(x[2 * n + 1], W[64 + j], b[j]));
}

__global__ void k_z1(const float* __restrict__ W, const float* __restrict__ b,
                     int N) {
    __shared__ float sW[64 * 64];
    for (int i = threadIdx.x; i < 64 * 64; i += blockDim.x) sW[i] = W[i];
    __syncthreads();
    int i = blockIdx.x * blockDim.x + threadIdx.x;
    if (i >= N * 64) return;
    int n = i >> 6, j = i & 63;
    const float* hr = &g_h[n * 64];
    float acc = b[j];
#pragma unroll
    for (int k = 0; k < 64; k++) acc = fmaf(hr[k], sW[k * 64 + j], acc);
    g_z[i] = acc;
}

// ============================================================
// per-layer init of accumulators
// ============================================================
__global__ void k_init(int N) {
    int i = blockIdx.x * blockDim.x + threadIdx.x;
    if (i < N * 64) g_out[i] = 0.f;
    if (i < N * 2) {
        g_m[i] = 0x00800000u;  // f2o(-FLT_MAX)
        g_denom[i] = 0.f;
    }
}

// ============================================================
// Pass A: alpha + segment max.  One warp per edge.
// lane l handles channels 2l, 2l+1. Heads split at lane 16.
// ============================================================
__global__ void k_passA(const int* __restrict__ ei, const float2* __restrict__ ea,
                        const float* __restrict__ We, const float* __restrict__ att,
                        int N, int E) {
    int gw = (blockIdx.x * blockDim.x + threadIdx.x) >> 5;
    int lane = threadIdx.x & 31;
    int EP = E + N;
    if (gw >= EP) return;
    int src, dst;
    float ea0, ea1;
    if (gw < E) {
        src = ei[gw];
        dst = ei[E + gw];
        float2 t = ea[gw];
        ea0 = t.x; ea1 = t.y;
    } else {
        src = dst = gw - E;
        ea0 = g_eamean[0]; ea1 = g_eamean[1];
    }
    int c = lane * 2;
    float2 zs = *(const float2*)&g_z[src * 64 + c];
    float2 zd = *(const float2*)&g_z[dst * 64 + c];
    float e0 = fmaf(ea0, We[c],     ea1 * We[64 + c]);
    float e1 = fmaf(ea0, We[c + 1], ea1 * We[64 + c + 1]);
    float s0 = zd.x + zs.x + e0; s0 = (s0 > 0.f) ? s0 : 0.2f * s0;
    float s1 = zd.y + zs.y + e1; s1 = (s1 > 0.f) ? s1 : 0.2f * s1;
    float p = fmaf(s0, att[c], s1 * att[c + 1]);
    // reduce within each 16-lane half (one head each)
    p += __shfl_xor_sync(0xffffffffu, p, 8);
    p += __shfl_xor_sync(0xffffffffu, p, 4);
    p += __shfl_xor_sync(0xffffffffu, p, 2);
    p += __shfl_xor_sync(0xffffffffu, p, 1);
    if ((lane & 15) == 0) {
        int h = lane >> 4;
        g_alpha[gw * 2 + h] = p;
        atomicMax(&g_m[dst * 2 + h], f2o(p));
    }
}

// ============================================================
// Pass B: exp + segment sum of exp.  One thread per edge.
// ============================================================
__global__ void k_passB(const int* __restrict__ ei, int N, int E) {
    int e = blockIdx.x * blockDim.x + threadIdx.x;
    int EP = E + N;
    if (e >= EP) return;
    int dst = (e < E) ? ei[E + e] : (e - E);
    float2 al = *(const float2*)&g_alpha[e * 2];
    float m0 = o2f(g_m[dst * 2]);
    float m1 = o2f(g_m[dst * 2 + 1]);
    float ex0 = expf(al.x - m0);
    float ex1 = expf(al.y - m1);
    asm volatile("red.global.add.v2.f32 [%0], {%1, %2};" ::
                 "l"(&g_denom[dst * 2]), "f"(ex0), "f"(ex1));
}

// ============================================================
// Pass C: weighted aggregate.  16 lanes per edge, 2 edges/warp.
// sub-lane s handles channels [4s, 4s+4) via v4 reductions.
// ============================================================
__global__ void k_passC(const int* __restrict__ ei, int N, int E) {
    int t = blockIdx.x * blockDim.x + threadIdx.x;
    int lane = threadIdx.x & 31;
    int e = (t >> 5) * 2 + (lane >> 4);
    int sub = lane & 15;
    int EP = E + N;
    if (e >= EP) return;
    int src, dst;
    if (e < E) { src = ei[e]; dst = ei[E + e]; }
    else       { src = dst = e - E; }
    int h = sub >> 3;  // channels [0,32) head0, [32,64) head1
    float al  = g_alpha[e * 2 + h];
    float m   = o2f(g_m[dst * 2 + h]);
    float den = g_denom[dst * 2 + h];
    float a = expf(al - m) / (den + 1e-16f);
    float4 z4 = *(const float4*)&g_z[src * 64 + sub * 4];
    float vx = z4.x * a, vy = z4.y * a, vz = z4.z * a, vw = z4.w * a;
    asm volatile("red.global.add.v4.f32 [%0], {%1, %2, %3, %4};" ::
                 "l"(&g_out[dst * 64 + sub * 4]),
                 "f"(vx), "f"(vy), "f"(vz), "f"(vw));
}

// ============================================================
// finalize: h = elu(out + bias)
// ============================================================
__global__ void k_final(const float* __restrict__ bias, int N) {
    int i = blockIdx.x * blockDim.x + threadIdx.x;
    if (i >= N * 64) return;
    float v = g_out[i] + bias[i & 63];
    g_h[i] = (v > 0.f) ? v : expm1f(v);
}

// ============================================================
// Head: u = h @ Wm1[0:64], v = h @ Wm1[64:128]
// ============================================================
__global__ void k_uv(const float* __restrict__ Wm1, int N) {
    __shared__ float sW[128 * 32];
    for (int i = threadIdx.x; i < 128 * 32; i += blockDim.x) sW[i] = Wm1[i];
    __syncthreads();
    int i = blockIdx.x * blockDim.x + threadIdx.x;
    if (i >= N * 64) return;
    int n = i >> 6, j = i & 63;
    int col = j & 31;
    int base = (j >> 5) * 64;  // 0 for u, 64 for v
    const float* hr = &g_h[n * 64];
    float acc = 0.f;
#pragma unroll
    for (int k = 0; k < 64; k++)
        acc = fmaf(hr[k], sW[(base + k) * 32 + col], acc);
    if (j < 32) g_u[n * 32 + col] = acc;
    else        g_v[n * 32 + col] = acc;
}

__global__ void k_gvec(const int* __restrict__ destp,
                       const float* __restrict__ Wm1,
                       const float* __restrict__ bm1) {
    int j = threadIdx.x;
    if (j >= 32) return;
    int dest = destp[0];
    float acc = bm1[j];
#pragma unroll
    for (int k = 0; k < 64; k++)
        acc = fmaf(g_h[dest * 64 + k], Wm1[(128 + k) * 32 + j], acc);
    g_gvec[j] = acc;
}

// ============================================================
// Edge scoring MLP: one warp per edge, lane = hidden channel.
// ============================================================
__global__ void k_edge(const int* __restrict__ ei, const float2* __restrict__ ea,
                       const float* __restrict__ Wm1, const float* __restrict__ Wm2,
                       const float* __restrict__ bm2, float* __restrict__ out,
                       int E) {
    int t = blockIdx.x * blockDim.x + threadIdx.x;
    int e = t >> 5;
    int j = t & 31;
    if (e >= E) return;
    int src = ei[e];
    int dst = ei[E + e];
    float2 a = ea[e];
    float hm = g_u[src * 32 + j] + g_v[dst * 32 + j] + g_gvec[j];
    hm = fmaf(a.x, Wm1[192 * 32 + j], hm);
    hm = fmaf(a.y, Wm1[193 * 32 + j], hm);
    hm = fmaxf(hm, 0.f);
    float p = hm * Wm2[j];
    p += __shfl_xor_sync(0xffffffffu, p, 16);
    p += __shfl_xor_sync(0xffffffffu, p, 8);
    p += __shfl_xor_sync(0xffffffffu, p, 4);
    p += __shfl_xor_sync(0xffffffffu, p, 2);
    p += __shfl_xor_sync(0xffffffffu, p, 1);
    if (j == 0) out[e] = p + bm2[0];
}

// ============================================================
extern "C" void kernel_launch(void* const* d_in, const int* in_sizes, int n_in,
                              void* d_out, int out_size) {
    const float* x     = (const float*)d_in[0];
    const int*   ei    = (const int*)d_in[1];
    const float* ea    = (const float*)d_in[2];
    const int*   dest  = (const int*)d_in[3];
    const float* W0    = (const float*)d_in[4];
    const float* b0    = (const float*)d_in[5];
    const float* We0   = (const float*)d_in[6];
    const float* att0  = (const float*)d_in[7];
    const float* bias0 = (const float*)d_in[8];
    const float* W1    = (const float*)d_in[9];
    const float* b1    = (const float*)d_in[10];
    const float* We1   = (const float*)d_in[11];
    const float* att1  = (const float*)d_in[12];
    const float* bias1 = (const float*)d_in[13];
    const float* Wm1   = (const float*)d_in[14];
    const float* bm1   = (const float*)d_in[15];
    const float* Wm2   = (const float*)d_in[16];
    const float* bm2   = (const float*)d_in[17];

    int N  = in_sizes[0] / 2;
    int E  = in_sizes[1] / 2;
    int EP = E + N;

    const int TB = 256;
    int gN64 = (N * 64 + TB - 1) / TB;
    int gA   = (EP * 32 + TB - 1) / TB;
    int gB   = (EP + TB - 1) / TB;
    int gC   = (EP * 16 + TB - 1) / TB;
    int gEdg = (E * 32 + TB - 1) / TB;

    // edge_attr mean (for self-loop fill)
    k_easum_init<<<1, 32>>>();
    k_easum<<<512, TB>>>((const float2*)ea, E);
    k_eamean<<<1, 32>>>(E);

    // ---- layer 0 ----
    k_z0<<<gN64, TB>>>(x, W0, b0, N);
    k_init<<<gN64, TB>>>(N);
    k_passA<<<gA, TB>>>(ei, (const float2*)ea, We0, att0, N, E);
    k_passB<<<gB, TB>>>(ei, N, E);
    k_passC<<<gC, TB>>>(ei, N, E);
    k_final<<<gN64, TB>>>(bias0, N);

    // ---- layer 1 ----
    k_z1<<<gN64, TB>>>(W1, b1, N);
    k_init<<<gN64, TB>>>(N);
    k_passA<<<gA, TB>>>(ei, (const float2*)ea, We1, att1, N, E);
    k_passB<<<gB, TB>>>(ei, N, E);
    k_passC<<<gC, TB>>>(ei, N, E);
    k_final<<<gN64, TB>>>(bias1, N);

    // ---- edge scoring head ----
    k_uv<<<gN64, TB>>>(Wm1, N);
    k_gvec<<<1, 32>>>(dest, Wm1, bm1);
    k_edge<<<gEdg, TB>>>(ei, (const float2*)ea, Wm1, Wm2, bm2,
                         (float*)d_out, E);
}

// round 2
// speedup vs baseline: 1.6596x; 1.6596x over previous
#include <cuda_runtime.h>
#include <math.h>

// Problem max sizes (N=50000, E=800000)
#define NMAX 50000
#define EMAX 800000

// ---- static device scratch (no allocation allowed) ----
__device__ float  g_za[NMAX * 64];     // layer-0 z  (x@W0+b0)
__device__ float  g_zb[NMAX * 64];     // layer-1 z  (h0@W1+b1)
__device__ float  g_u[NMAX * 32];      // h1 @ Wm1[0:64]
__device__ float  g_v[NMAX * 32];      // h1 @ Wm1[64:128]
__device__ float  g_hdest[64];         // h1 row of goal node
__device__ float  g_gvec[32];          // goal @ Wm1[128:192] + bm1
__device__ double g_easum[2];
__device__ float  g_eamean[2];
// CSR (edges sorted by dst), built once per launch, reused by both layers
__device__ int    g_cnt[NMAX];
__device__ int    g_rowptr[NMAX + 1];
__device__ int    g_rowcur[NMAX];
__device__ int    g_blocksum[256];
__device__ int    g_srcs[EMAX];
__device__ float2 g_eas[EMAX];

// ============================================================
// edge_attr column means (double accumulation)
// ============================================================
__global__ void k_easum_init() {
    if (threadIdx.x < 2) g_easum[threadIdx.x] = 0.0;
}

__global__ void k_easum(const float2* __restrict__ ea, int E) {
    double s0 = 0.0, s1 = 0.0;
    for (int i = blockIdx.x * blockDim.x + threadIdx.x; i < E;
         i += gridDim.x * blockDim.x) {
        float2 v = ea[i];
        s0 += (double)v.x; s1 += (double)v.y;
    }
    __shared__ double sh0[256], sh1[256];
    int t = threadIdx.x;
    sh0[t] = s0; sh1[t] = s1;
    __syncthreads();
    for (int ofs = 128; ofs > 0; ofs >>= 1) {
        if (t < ofs) { sh0[t] += sh0[t + ofs]; sh1[t] += sh1[t + ofs]; }
        __syncthreads();
    }
    if (t == 0) { atomicAdd(&g_easum[0], sh0[0]); atomicAdd(&g_easum[1], sh1[0]); }
}

__global__ void k_eamean(int E) {
    if (threadIdx.x < 2)
        g_eamean[threadIdx.x] = (float)(g_easum[threadIdx.x] / (double)E);
}

// ============================================================
// CSR build: histogram -> 2-level scan -> scatter
// ============================================================
__global__ void k_zero_cnt(int N) {
    int i = blockIdx.x * blockDim.x + threadIdx.x;
    if (i < N) g_cnt[i] = 0;
}

__global__ void k_hist(const int* __restrict__ ei, int E) {
    int e = blockIdx.x * blockDim.x + threadIdx.x;
    if (e < E) atomicAdd(&g_cnt[ei[E + e]], 1);
}

__global__ void k_scan1(int N) {
    __shared__ int sh[256];
    int i = blockIdx.x * 256 + threadIdx.x;
    sh[threadIdx.x] = (i < N) ? g_cnt[i] : 0;
    __syncthreads();
    for (int ofs = 1; ofs < 256; ofs <<= 1) {
        int t = (threadIdx.x >= (unsigned)ofs) ? sh[threadIdx.x - ofs] : 0;
        __syncthreads();
        sh[threadIdx.x] += t;
        __syncthreads();
    }
    if (i < N) g_rowptr[i + 1] = sh[threadIdx.x];   // block-local inclusive
    if (threadIdx.x == 255) g_blocksum[blockIdx.x] = sh[255];
}

__global__ void k_scan2(int nb) {
    __shared__ int sh[256];
    sh[threadIdx.x] = (threadIdx.x < (unsigned)nb) ? g_blocksum[threadIdx.x] : 0;
    __syncthreads();
    for (int ofs = 1; ofs < 256; ofs <<= 1) {
        int t = (threadIdx.x >= (unsigned)ofs) ? sh[threadIdx.x - ofs] : 0;
        __syncthreads();
        sh[threadIdx.x] += t;
        __syncthreads();
    }
    g_blocksum[threadIdx.x] = sh[threadIdx.x];      // inclusive
}

__global__ void k_scan3(int N) {
    int i = blockIdx.x * 256 + threadIdx.x;
    if (i >= N) return;
    int add = (i >= 256) ? g_blocksum[(i >> 8) - 1] : 0;
    int inc = g_rowptr[i + 1] + add;
    g_rowptr[i + 1] = inc;
    g_rowcur[i] = inc - g_cnt[i];                   // segment start
    if (i == 0) g_rowptr[0] = 0;
}

__global__ void k_scatter(const int* __restrict__ ei,
                          const float2* __restrict__ ea, int E) {
    int e = blockIdx.x * blockDim.x + threadIdx.x;
    if (e >= E) return;
    int dst = ei[E + e];
    int pos = atomicAdd(&g_rowcur[dst], 1);
    g_srcs[pos] = ei[e];
    g_eas[pos]  = ea[e];
}

// ============================================================
// z0 = x @ W0 + b0
// ============================================================
__global__ void k_z0(const float* __restrict__ x, const float* __restrict__ W,
                     const float* __restrict__ b, int N) {
    int i = blockIdx.x * blockDim.x + threadIdx.x;
    if (i >= N * 64) return;
    int n = i >> 6, j = i & 63;
    g_za[i] = fmaf(x[2 * n], W[j], fmaf(x[2 * n + 1], W[64 + j], b[j]));
}

// ============================================================
// Layer 0: online-softmax GATv2 aggregation, fused ELU + z1 GEMV.
// One warp per destination node; lane handles channels 2l,2l+1;
// heads split at lane 16.
// ============================================================
__global__ void __launch_bounds__(256)
k_agg0(const float* __restrict__ We, const float* __restrict__ att,
       const float* __restrict__ bias,
       const float* __restrict__ W1, const float* __restrict__ b1, int N) {
    __shared__ float sW[64 * 64];
    __shared__ float sh[8][64];
    for (int i = threadIdx.x; i < 64 * 64; i += blockDim.x) sW[i] = W1[i];
    __syncthreads();

    int warp = (blockIdx.x * blockDim.x + threadIdx.x) >> 5;
    int lane = threadIdx.x & 31;
    int ws   = threadIdx.x >> 5;
    bool active = warp < N;
    int dst = active ? warp : 0;
    int c = lane * 2;

    float We0a = We[c], We0b = We[c + 1];
    float We1a = We[64 + c], We1b = We[64 + c + 1];
    float at0 = att[c], at1 = att[c + 1];
    float2 zd = *(const float2*)&g_za[dst * 64 + c];

    float m = -INFINITY, denom = 0.f, acc0 = 0.f, acc1 = 0.f;
    int idx = g_rowptr[dst];
    int end = g_rowptr[dst + 1];

    // first iteration = self loop (src=dst, ea=mean); pipeline the z gather
    int   src = dst;
    float eax = g_eamean[0], eay = g_eamean[1];
    float2 zs = zd;
    for (;;) {
        bool more = idx < end;
        int nsrc = 0; float2 nea = make_float2(0.f, 0.f); float2 zn = zs;
        if (more) {
            nsrc = g_srcs[idx];
            nea  = g_eas[idx];
            zn   = *(const float2*)&g_za[nsrc * 64 + c];
        }
        float s0 = zd.x + zs.x + fmaf(eax, We0a, eay * We1a);
        float s1 = zd.y + zs.y + fmaf(eax, We0b, eay * We1b);
        s0 = (s0 > 0.f) ? s0 : 0.2f * s0;
        s1 = (s1 > 0.f) ? s1 : 0.2f * s1;
        float p = fmaf(s0, at0, s1 * at1);
        p += __shfl_xor_sync(0xffffffffu, p, 8);
        p += __shfl_xor_sync(0xffffffffu, p, 4);
        p += __shfl_xor_sync(0xffffffffu, p, 2);
        p += __shfl_xor_sync(0xffffffffu, p, 1);
        float mn = fmaxf(m, p);
        float sc = expf(m - mn);
        float w  = expf(p - mn);
        denom = denom * sc + w;
        acc0  = fmaf(acc0, sc, w * zs.x);
        acc1  = fmaf(acc1, sc, w * zs.y);
        m = mn;
        if (!more) break;
        src = nsrc; eax = nea.x; eay = nea.y; zs = zn; idx++;
    }
    float inv = 1.f / (denom + 1e-16f);
    float o0 = acc0 * inv + bias[c];
    float o1 = acc1 * inv + bias[c + 1];
    float h0 = (o0 > 0.f) ? o0 : expm1f(o0);
    float h1 = (o1 > 0.f) ? o1 : expm1f(o1);

    // epilogue: z1 = h @ W1 + b1 (h staged in smem, per-warp)
    sh[ws][c] = h0; sh[ws][c + 1] = h1;
    __syncwarp();
    float za = b1[c], zb = b1[c + 1];
#pragma unroll
    for (int k = 0; k < 64; k++) {
        float hv = sh[ws][k];
        za = fmaf(hv, sW[k * 64 + c], za);
        zb = fmaf(hv, sW[k * 64 + c + 1], zb);
    }
    if (active) {
        g_zb[dst * 64 + c]     = za;
        g_zb[dst * 64 + c + 1] = zb;
    }
}

// ============================================================
// Layer 1: same aggregation, fused ELU + (u,v)=h@Wm1 + goal capture.
// ============================================================
__global__ void __launch_bounds__(256)
k_agg1(const float* __restrict__ We, const float* __restrict__ att,
       const float* __restrict__ bias,
       const float* __restrict__ Wm1, const int* __restrict__ destp, int N) {
    __shared__ float sW[128 * 32];
    __shared__ float sh[8][64];
    for (int i = threadIdx.x; i < 128 * 32; i += blockDim.x) sW[i] = Wm1[i];
    __syncthreads();

    int warp = (blockIdx.x * blockDim.x + threadIdx.x) >> 5;
    int lane = threadIdx.x & 31;
    int ws   = threadIdx.x >> 5;
    bool active = warp < N;
    int dst = active ? warp : 0;
    int c = lane * 2;

    float We0a = We[c], We0b = We[c + 1];
    float We1a = We[64 + c], We1b = We[64 + c + 1];
    float at0 = att[c], at1 = att[c + 1];
    float2 zd = *(const float2*)&g_zb[dst * 64 + c];

    float m = -INFINITY, denom = 0.f, acc0 = 0.f, acc1 = 0.f;
    int idx = g_rowptr[dst];
    int end = g_rowptr[dst + 1];

    int   src = dst;
    float eax = g_eamean[0], eay = g_eamean[1];
    float2 zs = zd;
    for (;;) {
        bool more = idx < end;
        int nsrc = 0; float2 nea = make_float2(0.f, 0.f); float2 zn = zs;
        if (more) {
            nsrc = g_srcs[idx];
            nea  = g_eas[idx];
            zn   = *(const float2*)&g_zb[nsrc * 64 + c];
        }
        float s0 = zd.x + zs.x + fmaf(eax, We0a, eay * We1a);
        float s1 = zd.y + zs.y + fmaf(eax, We0b, eay * We1b);
        s0 = (s0 > 0.f) ? s0 : 0.2f * s0;
        s1 = (s1 > 0.f) ? s1 : 0.2f * s1;
        float p = fmaf(s0, at0, s1 * at1);
        p += __shfl_xor_sync(0xffffffffu, p, 8);
        p += __shfl_xor_sync(0xffffffffu, p, 4);
        p += __shfl_xor_sync(0xffffffffu, p, 2);
        p += __shfl_xor_sync(0xffffffffu, p, 1);
        float mn = fmaxf(m, p);
        float sc = expf(m - mn);
        float w  = expf(p - mn);
        denom = denom * sc + w;
        acc0  = fmaf(acc0, sc, w * zs.x);
        acc1  = fmaf(acc1, sc, w * zs.y);
        m = mn;
        if (!more) break;
        src = nsrc; eax = nea.x; eay = nea.y; zs = zn; idx++;
    }
    float inv = 1.f / (denom + 1e-16f);
    float o0 = acc0 * inv + bias[c];
    float o1 = acc1 * inv + bias[c + 1];
    float h0 = (o0 > 0.f) ? o0 : expm1f(o0);
    float h1 = (o1 > 0.f) ? o1 : expm1f(o1);

    if (active && dst == destp[0]) {
        g_hdest[c] = h0; g_hdest[c + 1] = h1;
    }

    // epilogue: u = h@Wm1[0:64], v = h@Wm1[64:128]; lane -> column
    sh[ws][c] = h0; sh[ws][c + 1] = h1;
    __syncwarp();
    float ua = 0.f, va = 0.f;
#pragma unroll
    for (int k = 0; k < 64; k++) {
        float hv = sh[ws][k];
        ua = fmaf(hv, sW[k * 32 + lane], ua);
        va = fmaf(hv, sW[(64 + k) * 32 + lane], va);
    }
    if (active) {
        g_u[dst * 32 + lane] = ua;
        g_v[dst * 32 + lane] = va;
    }
}

// ============================================================
// gvec = h[dest] @ Wm1[128:192] + bm1
// ============================================================
__global__ void k_gvec(const float* __restrict__ Wm1,
                       const float* __restrict__ bm1) {
    int j = threadIdx.x;
    if (j >= 32) return;
    float acc = bm1[j];
#pragma unroll
    for (int k = 0; k < 64; k++)
        acc = fmaf(g_hdest[k], Wm1[(128 + k) * 32 + j], acc);
    g_gvec[j] = acc;
}

// ============================================================
// Edge scoring MLP: one warp per edge, lane = hidden channel.
// ============================================================
__global__ void k_edge(const int* __restrict__ ei, const float2* __restrict__ ea,
                       const float* __restrict__ Wm1, const float* __restrict__ Wm2,
                       const float* __restrict__ bm2, float* __restrict__ out,
                       int E) {
    int t = blockIdx.x * blockDim.x + threadIdx.x;
    int e = t >> 5;
    int j = t & 31;
    if (e >= E) return;
    int src = ei[e];
    int dst = ei[E + e];
    float2 a = ea[e];
    float hm = g_u[src * 32 + j] + g_v[dst * 32 + j] + g_gvec[j];
    hm = fmaf(a.x, Wm1[192 * 32 + j], hm);
    hm = fmaf(a.y, Wm1[193 * 32 + j], hm);
    hm = fmaxf(hm, 0.f);
    float p = hm * Wm2[j];
    p += __shfl_xor_sync(0xffffffffu, p, 16);
    p += __shfl_xor_sync(0xffffffffu, p, 8);
    p += __shfl_xor_sync(0xffffffffu, p, 4);
    p += __shfl_xor_sync(0xffffffffu, p, 2);
    p += __shfl_xor_sync(0xffffffffu, p, 1);
    if (j == 0) out[e] = p + bm2[0];
}

// ============================================================
extern "C" void kernel_launch(void* const* d_in, const int* in_sizes, int n_in,
                              void* d_out, int out_size) {
    const float* x     = (const float*)d_in[0];
    const int*   ei    = (const int*)d_in[1];
    const float* ea    = (const float*)d_in[2];
    const int*   dest  = (const int*)d_in[3];
    const float* W0    = (const float*)d_in[4];
    const float* b0    = (const float*)d_in[5];
    const float* We0   = (const float*)d_in[6];
    const float* att0  = (const float*)d_in[7];
    const float* bias0 = (const float*)d_in[8];
    const float* W1    = (const float*)d_in[9];
    const float* b1    = (const float*)d_in[10];
    const float* We1   = (const float*)d_in[11];
    const float* att1  = (const float*)d_in[12];
    const float* bias1 = (const float*)d_in[13];
    const float* Wm1   = (const float*)d_in[14];
    const float* bm1   = (const float*)d_in[15];
    const float* Wm2   = (const float*)d_in[16];
    const float* bm2   = (const float*)d_in[17];

    int N = in_sizes[0] / 2;
    int E = in_sizes[1] / 2;

    const int TB = 256;
    int gN   = (N + TB - 1) / TB;
    int gE   = (E + TB - 1) / TB;
    int gN64 = (N * 64 + TB - 1) / TB;
    int gAgg = (N * 32 + TB - 1) / TB;      // warp per node
    int gEdg = (E * 32 + TB - 1) / TB;      // warp per edge
    int nSB  = (N + 255) / 256;             // scan blocks (<=256)

    // edge_attr mean (self-loop fill value)
    k_easum_init<<<1, 32>>>();
    k_easum<<<512, TB>>>((const float2*)ea, E);
    k_eamean<<<1, 32>>>(E);

    // CSR build (by dst), shared by both layers
    k_zero_cnt<<<gN, TB>>>(N);
    k_hist<<<gE, TB>>>(ei, E);
    k_scan1<<<nSB, 256>>>(N);
    k_scan2<<<1, 256>>>(nSB);
    k_scan3<<<nSB, 256>>>(N);
    k_scatter<<<gE, TB>>>(ei, (const float2*)ea, E);

    // layer 0 (fused: agg + elu + z1 GEMV)
    k_z0<<<gN64, TB>>>(x, W0, b0, N);
    k_agg0<<<gAgg, TB>>>(We0, att0, bias0, W1, b1, N);

    // layer 1 (fused: agg + elu + u/v GEMV + goal capture)
    k_agg1<<<gAgg, TB>>>(We1, att1, bias1, Wm1, dest, N);

    // edge scoring head
    k_gvec<<<1, 32>>>(Wm1, bm1);
    k_edge<<<gEdg, TB>>>(ei, (const float2*)ea, Wm1, Wm2, bm2,
                         (float*)d_out, E);
}

// round 3
// speedup vs baseline: 2.1935x; 1.3217x over previous
#include <cuda_runtime.h>
#include <math.h>

// Problem max sizes (N=50000, E=800000)
#define NMAX 50000
#define EMAX 800000

// ---- static device scratch ----
__device__ float  g_za[NMAX * 64];     // layer-0 z
__device__ float  g_zb[NMAX * 64];     // layer-1 z
__device__ float  g_u[NMAX * 32];      // h1 @ Wm1[0:64]
__device__ float  g_v[NMAX * 32];      // h1 @ Wm1[64:128]
__device__ float  g_hdest[64];
__device__ float  g_gvec[32];
__device__ double g_easum[2];
__device__ float  g_eamean[2];
// CSR by dst
__device__ int    g_cnt[NMAX];
__device__ int    g_rowptr[NMAX + 1];
__device__ int    g_rowcur[NMAX];
__device__ int    g_srcs[EMAX];
__device__ int    g_edst[EMAX];
__device__ int    g_eperm[EMAX];
__device__ float2 g_eas[EMAX];
// decoupled-lookback scan state
__device__ unsigned long long g_tile[256];
__device__ int    g_tilectr;

// ============================================================
// 0) init: zero cnt / easum / scan state
// ============================================================
__global__ void k_init(int N) {
    int i = blockIdx.x * blockDim.x + threadIdx.x;
    if (i < N) g_cnt[i] = 0;
    if (i < 256) g_tile[i] = 0ull;
    if (i == 0) { g_tilectr = 0; g_easum[0] = 0.0; g_easum[1] = 0.0; }
}

// ============================================================
// 1) fused: edge_attr column sums (double) + dst histogram
// ============================================================
__global__ void k_easum_hist(const int* __restrict__ ei,
                             const float2* __restrict__ ea, int E) {
    double d0 = 0.0, d1 = 0.0;
    for (int i = blockIdx.x * blockDim.x + threadIdx.x; i < E;
         i += gridDim.x * blockDim.x) {
        float2 v = ea[i];
        d0 += (double)v.x; d1 += (double)v.y;
        atomicAdd(&g_cnt[ei[E + i]], 1);
    }
    __shared__ double sh0[256], sh1[256];
    int t = threadIdx.x;
    sh0[t] = d0; sh1[t] = d1;
    __syncthreads();
    for (int ofs = 128; ofs > 0; ofs >>= 1) {
        if (t < ofs) { sh0[t] += sh0[t + ofs]; sh1[t] += sh1[t + ofs]; }
        __syncthreads();
    }
    if (t == 0) { atomicAdd(&g_easum[0], sh0[0]); atomicAdd(&g_easum[1], sh1[0]); }
}

// ============================================================
// 2) single-kernel exclusive scan of g_cnt (decoupled lookback)
//    also computes g_eamean (block ticket 0)
// ============================================================
__global__ void __launch_bounds__(256) k_scan(int N, int E) {
    __shared__ int sbid;
    __shared__ int swsum[8];
    __shared__ int sexcl;
    if (threadIdx.x == 0) sbid = atomicAdd(&g_tilectr, 1);
    __syncthreads();
    int bid = sbid;
    if (bid == 0 && threadIdx.x < 2)
        g_eamean[threadIdx.x] = (float)(g_easum[threadIdx.x] / (double)E);

    int i = bid * 256 + threadIdx.x;
    int v = (i < N) ? g_cnt[i] : 0;
    int lane = threadIdx.x & 31, w = threadIdx.x >> 5;
    int s = v;
#pragma unroll
    for (int o = 1; o < 32; o <<= 1) {
        int t = __shfl_up_sync(0xffffffffu, s, o);
        if (lane >= o) s += t;
    }
    if (lane == 31) swsum[w] = s;
    __syncthreads();
    if (w == 0) {
        int ws = (lane < 8) ? swsum[lane] : 0;
#pragma unroll
        for (int o = 1; o < 8; o <<= 1) {
            int t = __shfl_up_sync(0xffffffffu, ws, o);
            if (lane >= o) ws += t;
        }
        if (lane < 8) swsum[lane] = ws;
    }
    __syncthreads();
    int incl = s + (w > 0 ? swsum[w - 1] : 0);
    int btotal = swsum[7];

    if (threadIdx.x == 0) {
        unsigned long long word = (bid == 0)
            ? ((2ull << 32) | (unsigned)btotal)    // block0: inclusive prefix
            : ((1ull << 32) | (unsigned)btotal);   // aggregate
        atomicExch(&g_tile[bid], word);
    }

    if (bid > 0 && w == 0) {
        int excl = 0;
        int look = bid - 1 - lane;     // lane0 = nearest predecessor
        for (;;) {
            unsigned long long word = (look >= 0)
                ? atomicAdd(&g_tile[look], 0ull) : (2ull << 32);
            unsigned st = (unsigned)(word >> 32);
            unsigned pend = __ballot_sync(0xffffffffu, st == 0u);
            if (pend) continue;
            unsigned pre = __ballot_sync(0xffffffffu, st == 2u);
            int fp = __ffs(pre) - 1;   // nearest lane holding an inclusive prefix
            int val = (int)(word & 0xffffffffu);
            if (fp >= 0) {
                int contrib = (lane <= fp && look >= 0) ? val : 0;
#pragma unroll
                for (int o = 16; o > 0; o >>= 1)
                    contrib += __shfl_xor_sync(0xffffffffu, contrib, o);
                excl += contrib;
                break;
            } else {
                int contrib = (look >= 0) ? val : 0;
#pragma unroll
                for (int o = 16; o > 0; o >>= 1)
                    contrib += __shfl_xor_sync(0xffffffffu, contrib, o);
                excl += contrib;
                look -= 32;
            }
        }
        if (lane == 0) {
            atomicExch(&g_tile[bid], (2ull << 32) | (unsigned)(excl + btotal));
            sexcl = excl;
        }
    } else if (threadIdx.x == 0) {
        sexcl = 0;
    }
    __syncthreads();
    int excl = sexcl;
    if (i < N) {
        int ip = excl + incl;
        g_rowptr[i + 1] = ip;
        g_rowcur[i] = ip - v;
    }
    if (i == 0) g_rowptr[0] = 0;
}

// ============================================================
// 3) fused: CSR scatter + z0 = x@W0+b0  (block-partitioned)
// ============================================================
__global__ void k_scatter_z0(const int* __restrict__ ei,
                             const float2* __restrict__ ea,
                             const float* __restrict__ x,
                             const float* __restrict__ W0,
                             const float* __restrict__ b0,
                             int N, int E, int gE) {
    if ((int)blockIdx.x < gE) {
        int e = blockIdx.x * 256 + threadIdx.x;
        if (e < E) {
            int dst = ei[E + e];
            int pos = atomicAdd(&g_rowcur[dst], 1);
            g_srcs[pos]  = ei[e];
            g_edst[pos]  = dst;
            g_eperm[pos] = e;
            g_eas[pos]   = ea[e];
        }
    } else {
        int i = (blockIdx.x - gE) * 256 + threadIdx.x;
        if (i < N * 64) {
            int n = i >> 6, j = i & 63;
            g_za[i] = fmaf(x[2 * n], W0[j], fmaf(x[2 * n + 1], W0[64 + j], b0[j]));
        }
    }
}

// ============================================================
// GATv2 online-softmax aggregation core (warp per dst node).
// lane handles channels c=2*lane, c+1; heads split at lane 16.
// Unrolled by 2 edges for ILP on gathers / shuffles / exp.
// ============================================================
__device__ __forceinline__ void gat_agg(const float* __restrict__ zbase,
                                        int dst, int lane, int c,
                                        const float* __restrict__ We,
                                        const float* __restrict__ att,
                                        const float* __restrict__ bias,
                                        float& h0, float& h1) {
    float We0a = We[c],      We0b = We[c + 1];
    float We1a = We[64 + c], We1b = We[64 + c + 1];
    float at0 = att[c], at1 = att[c + 1];
    float2 zd = __ldg((const float2*)&zbase[dst * 64 + c]);

    // self loop (src=dst, ea=mean)
    float eax = g_eamean[0], eay = g_eamean[1];
    float s0 = zd.x + zd.x + fmaf(eax, We0a, eay * We1a);
    float s1 = zd.y + zd.y + fmaf(eax, We0b, eay * We1b);
    s0 = (s0 > 0.f) ? s0 : 0.2f * s0;
    s1 = (s1 > 0.f) ? s1 : 0.2f * s1;
    float p = fmaf(s0, at0, s1 * at1);
#pragma unroll
    for (int o = 8; o >= 1; o >>= 1) p += __shfl_xor_sync(0xffffffffu, p, o);
    float m = p, denom = 1.f, acc0 = zd.x, acc1 = zd.y;

    int idx = g_rowptr[dst], end = g_rowptr[dst + 1];
    for (; idx + 2 <= end; idx += 2) {
        int sa = g_srcs[idx], sb = g_srcs[idx + 1];
        float2 eaA = g_eas[idx], eaB = g_eas[idx + 1];
        float2 za = __ldg((const float2*)&zbase[sa * 64 + c]);
        float2 zb = __ldg((const float2*)&zbase[sb * 64 + c]);

        float a0 = zd.x + za.x + fmaf(eaA.x, We0a, eaA.y * We1a);
        float a1 = zd.y + za.y + fmaf(eaA.x, We0b, eaA.y * We1b);
        float b0_ = zd.x + zb.x + fmaf(eaB.x, We0a, eaB.y * We1a);
        float b1_ = zd.y + zb.y + fmaf(eaB.x, We0b, eaB.y * We1b);
        a0 = (a0 > 0.f) ? a0 : 0.2f * a0;
        a1 = (a1 > 0.f) ? a1 : 0.2f * a1;
        b0_ = (b0_ > 0.f) ? b0_ : 0.2f * b0_;
        b1_ = (b1_ > 0.f) ? b1_ : 0.2f * b1_;
        float pa = fmaf(a0, at0, a1 * at1);
        float pb = fmaf(b0_, at0, b1_ * at1);
#pragma unroll
        for (int o = 8; o >= 1; o >>= 1) {
            pa += __shfl_xor_sync(0xffffffffu, pa, o);
            pb += __shfl_xor_sync(0xffffffffu, pb, o);
        }
        float mn = fmaxf(m, fmaxf(pa, pb));
        float sc = __expf(m - mn);
        float wa = __expf(pa - mn);
        float wb = __expf(pb - mn);
        denom = fmaf(denom, sc, wa + wb);
        acc0 = fmaf(acc0, sc, fmaf(wa, za.x, wb * zb.x));
        acc1 = fmaf(acc1, sc, fmaf(wa, za.y, wb * zb.y));
        m = mn;
    }
    if (idx < end) {
        int sa = g_srcs[idx];
        float2 eaA = g_eas[idx];
        float2 za = __ldg((const float2*)&zbase[sa * 64 + c]);
        float a0 = zd.x + za.x + fmaf(eaA.x, We0a, eaA.y * We1a);
        float a1 = zd.y + za.y + fmaf(eaA.x, We0b, eaA.y * We1b);
        a0 = (a0 > 0.f) ? a0 : 0.2f * a0;
        a1 = (a1 > 0.f) ? a1 : 0.2f * a1;
        float pa = fmaf(a0, at0, a1 * at1);
#pragma unroll
        for (int o = 8; o >= 1; o >>= 1) pa += __shfl_xor_sync(0xffffffffu, pa, o);
        float mn = fmaxf(m, pa);
        float sc = __expf(m - mn);
        float wa = __expf(pa - mn);
        denom = fmaf(denom, sc, wa);
        acc0 = fmaf(acc0, sc, wa * za.x);
        acc1 = fmaf(acc1, sc, wa * za.y);
        m = mn;
    }
    float inv = __fdividef(1.f, denom + 1e-16f);
    float o0 = fmaf(acc0, inv, bias[c]);
    float o1 = fmaf(acc1, inv, bias[c + 1]);
    h0 = (o0 > 0.f) ? o0 : expm1f(o0);
    h1 = (o1 > 0.f) ? o1 : expm1f(o1);
}

// ============================================================
// 4) layer 0: agg + ELU + fused z1 = h@W1+b1
// ============================================================
__global__ void __launch_bounds__(256)
k_agg0(const float* __restrict__ We, const float* __restrict__ att,
       const float* __restrict__ bias,
       const float* __restrict__ W1, const float* __restrict__ b1, int N) {
    __shared__ float sW[64 * 64];
    __shared__ float sh[8][64];
    for (int i = threadIdx.x; i < 64 * 64; i += blockDim.x) sW[i] = W1[i];
    __syncthreads();

    int warp = (blockIdx.x * blockDim.x + threadIdx.x) >> 5;
    int lane = threadIdx.x & 31;
    int ws = threadIdx.x >> 5;
    bool active = warp < N;
    int dst = active ? warp : 0;
    int c = lane * 2;

    float h0, h1;
    gat_agg(g_za, dst, lane, c, We, att, bias, h0, h1);

    sh[ws][c] = h0; sh[ws][c + 1] = h1;
    __syncwarp();
    float za = b1[c], zb = b1[c + 1];
#pragma unroll
    for (int k = 0; k < 64; k++) {
        float hv = sh[ws][k];
        float2 w2 = *(const float2*)&sW[k * 64 + c];
        za = fmaf(hv, w2.x, za);
        zb = fmaf(hv, w2.y, zb);
    }
    if (active) {
        g_zb[dst * 64 + c]     = za;
        g_zb[dst * 64 + c + 1] = zb;
    }
}

// ============================================================
// 5) layer 1: agg + ELU + fused u/v = h@Wm1[0:128] + goal capture
// ============================================================
__global__ void __launch_bounds__(256)
k_agg1(const float* __restrict__ We, const float* __restrict__ att,
       const float* __restrict__ bias,
       const float* __restrict__ Wm1, const int* __restrict__ destp, int N) {
    __shared__ float sW[128 * 32];
    __shared__ float sh[8][64];
    for (int i = threadIdx.x; i < 128 * 32; i += blockDim.x) sW[i] = Wm1[i];
    __syncthreads();

    int warp = (blockIdx.x * blockDim.x + threadIdx.x) >> 5;
    int lane = threadIdx.x & 31;
    int ws = threadIdx.x >> 5;
    bool active = warp < N;
    int dst = active ? warp : 0;
    int c = lane * 2;

    float h0, h1;
    gat_agg(g_zb, dst, lane, c, We, att, bias, h0, h1);

    if (active && dst == destp[0]) {
        g_hdest[c] = h0; g_hdest[c + 1] = h1;
    }

    sh[ws][c] = h0; sh[ws][c + 1] = h1;
    __syncwarp();
    float ua = 0.f, va = 0.f;
#pragma unroll
    for (int k = 0; k < 64; k++) {
        float hv = sh[ws][k];
        ua = fmaf(hv, sW[k * 32 + lane], ua);
        va = fmaf(hv, sW[(64 + k) * 32 + lane], va);
    }
    if (active) {
        g_u[dst * 32 + lane] = ua;
        g_v[dst * 32 + lane] = va;
    }
}

// ============================================================
// 6) gvec = h[dest] @ Wm1[128:192] + bm1
// ============================================================
__global__ void k_gvec(const float* __restrict__ Wm1,
                       const float* __restrict__ bm1) {
    int j = threadIdx.x;
    if (j >= 32) return;
    float acc = bm1[j];
#pragma unroll
    for (int k = 0; k < 64; k++)
        acc = fmaf(g_hdest[k], Wm1[(128 + k) * 32 + j], acc);
    g_gvec[j] = acc;
}

// ============================================================
// 7) edge MLP in CSR order: 8 lanes per edge, float4 channels.
// ============================================================
__global__ void k_edge(const float* __restrict__ Wm1,
                       const float* __restrict__ Wm2,
                       const float* __restrict__ bm2,
                       float* __restrict__ out, int E) {
    int t = blockIdx.x * blockDim.x + threadIdx.x;
    int p = t >> 3;
    int l = t & 7;
    if (p >= E) return;
    int src = g_srcs[p];
    int dst = g_edst[p];
    float2 a = g_eas[p];
    float4 u4 = __ldg((const float4*)&g_u[src * 32 + l * 4]);
    float4 v4 = __ldg((const float4*)&g_v[dst * 32 + l * 4]);
    float4 gv = *(const float4*)&g_gvec[l * 4];
    float4 w0 = __ldg(&((const float4*)&Wm1[192 * 32])[l]);
    float4 w1 = __ldg(&((const float4*)&Wm1[193 * 32])[l]);
    float4 w2 = __ldg(&((const float4*)Wm2)[l]);

    float m0 = u4.x + v4.x + gv.x + fmaf(a.x, w0.x, a.y * w1.x);
    float m1 = u4.y + v4.y + gv.y + fmaf(a.x, w0.y, a.y * w1.y);
    float m2 = u4.z + v4.z + gv.z + fmaf(a.x, w0.z, a.y * w1.z);
    float m3 = u4.w + v4.w + gv.w + fmaf(a.x, w0.w, a.y * w1.w);
    m0 = fmaxf(m0, 0.f); m1 = fmaxf(m1, 0.f);
    m2 = fmaxf(m2, 0.f); m3 = fmaxf(m3, 0.f);
    float s = fmaf(m0, w2.x, fmaf(m1, w2.y, fmaf(m2, w2.z, m3 * w2.w)));
    s += __shfl_xor_sync(0xffffffffu, s, 4);
    s += __shfl_xor_sync(0xffffffffu, s, 2);
    s += __shfl_xor_sync(0xffffffffu, s, 1);
    if (l == 0) out[g_eperm[p]] = s + bm2[0];
}

// ============================================================
extern "C" void kernel_launch(void* const* d_in, const int* in_sizes, int n_in,
                              void* d_out, int out_size) {
    const float* x     = (const float*)d_in[0];
    const int*   ei    = (const int*)d_in[1];
    const float* ea    = (const float*)d_in[2];
    const int*   dest  = (const int*)d_in[3];
    const float* W0    = (const float*)d_in[4];
    const float* b0    = (const float*)d_in[5];
    const float* We0   = (const float*)d_in[6];
    const float* att0  = (const float*)d_in[7];
    const float* bias0 = (const float*)d_in[8];
    const float* W1    = (const float*)d_in[9];
    const float* b1    = (const float*)d_in[10];
    const float* We1   = (const float*)d_in[11];
    const float* att1  = (const float*)d_in[12];
    const float* bias1 = (const float*)d_in[13];
    const float* Wm1   = (const float*)d_in[14];
    const float* bm1   = (const float*)d_in[15];
    const float* Wm2   = (const float*)d_in[16];
    const float* bm2   = (const float*)d_in[17];

    int N = in_sizes[0] / 2;
    int E = in_sizes[1] / 2;

    const int TB = 256;
    int gN    = (N + TB - 1) / TB;
    int gE    = (E + TB - 1) / TB;
    int gN64  = (N * 64 + TB - 1) / TB;
    int gAgg  = (N * 32 + TB - 1) / TB;
    int gEdg8 = (E * 8 + TB - 1) / TB;
    int nSB   = (N + 255) / 256;

    int gInit = (gN > 1) ? gN : 1;

    // launch order chosen so ncu (-s 5 -c 1) profiles k_agg1 (index 5)
    k_init<<<gInit, TB>>>(N);                                           // 0
    k_easum_hist<<<512, TB>>>(ei, (const float2*)ea, E);                // 1
    k_scan<<<nSB, 256>>>(N, E);                                         // 2
    k_scatter_z0<<<gE + gN64, TB>>>(ei, (const float2*)ea, x,
                                    W0, b0, N, E, gE);                  // 3
    k_agg0<<<gAgg, TB>>>(We0, att0, bias0, W1, b1, N);                  // 4
    k_agg1<<<gAgg, TB>>>(We1, att1, bias1, Wm1, dest, N);               // 5
    k_gvec<<<1, 32>>>(Wm1, bm1);                                        // 6
    k_edge<<<gEdg8, TB>>>(Wm1, Wm2, bm2, (float*)d_out, E);             // 7
}